// round 16
// baseline (speedup 1.0000x reference)
#include <cuda_runtime.h>
#include <cuda_fp16.h>
#include <cstdint>

#define BATCH 4
#define SEQ   2048
#define EMB   1024
#define HDIM  1024
#define MROWS (BATCH*SEQ)

#define KCHUNK        16
#define ROW_HALVES    24                      // 16 data halves + 8 pad (48B pitch, conflict-free)
#define A_TILE_HALVES (256*ROW_HALVES)        // 6144 halves = 12288 B
#define B_TILE_HALVES (128*ROW_HALVES)        // 3072 halves = 6144 B
#define A_TILE_B      (A_TILE_HALVES*2)
#define B_TILE_B      (B_TILE_HALVES*2)
#define STAGE_HALVES  (A_TILE_HALVES + 2*B_TILE_HALVES)   // 12288 halves
#define STAGE_B       (STAGE_HALVES*2)                    // 24576 B
// static smem: 2*STAGE_B = 49152 B = 48 KB exactly (proven cap)

#define GEMM_THREADS 256                      // 8 warps of 64x64 over a 256x128 tile

// ---------------- device scratch ----------------
__device__ __half g_Xh [(size_t)MROWS*EMB];                // X hi only (A side)
__device__ __half g_Wh [(size_t)3*HDIM*EMB];
__device__ __half g_Wl [(size_t)3*HDIM*EMB];
__device__ __half g_Qh [(size_t)MROWS*HDIM];               // Q hi only (A side)
__device__ __half g_Kh [(size_t)MROWS*HDIM];
__device__ __half g_Kl [(size_t)MROWS*HDIM];
__device__ __half g_Vth[(size_t)BATCH*HDIM*SEQ];           // [b][d][s]
__device__ __half g_Vtl[(size_t)BATCH*HDIM*SEQ];
__device__ float  g_S  [(size_t)BATCH*SEQ*SEQ];
__device__ __half g_Ph [(size_t)BATCH*SEQ*SEQ];            // P hi only (A side)

// ---------------- helpers ----------------
__device__ __forceinline__ uint32_t smem_u32(const void* p) {
    uint32_t a;
    asm("{ .reg .u64 t; cvta.to.shared.u64 t, %1; cvt.u32.u64 %0, t; }" : "=r"(a) : "l"(p));
    return a;
}
__device__ __forceinline__ void cp16(uint32_t saddr, const void* g) {
    asm volatile("cp.async.cg.shared.global [%0], [%1], 16;" :: "r"(saddr), "l"(g));
}
#define CP_COMMIT() asm volatile("cp.async.commit_group;" ::: "memory")
#define CP_WAIT1()  asm volatile("cp.async.wait_group 1;" ::: "memory")
#define CP_WAIT0()  asm volatile("cp.async.wait_group 0;" ::: "memory")

#define MMA(c, a, b) \
    asm volatile("mma.sync.aligned.m16n8k16.row.col.f32.f16.f16.f32 " \
        "{%0,%1,%2,%3}, {%4,%5,%6,%7}, {%8,%9}, {%0,%1,%2,%3};" \
        : "+f"((c)[0]), "+f"((c)[1]), "+f"((c)[2]), "+f"((c)[3]) \
        : "r"((a)[0]), "r"((a)[1]), "r"((a)[2]), "r"((a)[3]), "r"((b)[0]), "r"((b)[1]))

__device__ __forceinline__ uint16_t hi16(float x) {
    return __half_as_ushort(__float2half(x));
}
__device__ __forceinline__ void split2h(float x, uint16_t& h, uint16_t& l) {
    __half hb = __float2half(x);
    __half lb = __float2half(x - __half2float(hb));
    h = __half_as_ushort(hb);
    l = __half_as_ushort(lb);
}
__device__ __forceinline__ uint32_t pack2(uint16_t a, uint16_t b) {
    return (uint32_t)a | ((uint32_t)b << 16);
}

// ---------------- split kernels ----------------
__global__ __launch_bounds__(256) void split_x_kernel(const float* __restrict__ src) {
    size_t i = ((size_t)blockIdx.x * 256 + threadIdx.x) * 4;
    float4 v = *(const float4*)(src + i);
    *(uint2*)((uint16_t*)g_Xh + i) =
        make_uint2(pack2(hi16(v.x), hi16(v.y)), pack2(hi16(v.z), hi16(v.w)));
}
__global__ __launch_bounds__(256) void split_w_kernel(
    const float* __restrict__ Wq, const float* __restrict__ Wk, const float* __restrict__ Wv)
{
    const int z = blockIdx.y;
    const float* src = (z == 0) ? Wq : (z == 1) ? Wk : Wv;
    size_t i = ((size_t)blockIdx.x * 256 + threadIdx.x) * 4;
    size_t off = (size_t)z * HDIM * EMB;
    float4 v = *(const float4*)(src + i);
    uint16_t h[4], l[4];
    split2h(v.x, h[0], l[0]); split2h(v.y, h[1], l[1]);
    split2h(v.z, h[2], l[2]); split2h(v.w, h[3], l[3]);
    *(uint2*)((uint16_t*)g_Wh + off + i) = make_uint2(pack2(h[0], h[1]), pack2(h[2], h[3]));
    *(uint2*)((uint16_t*)g_Wl + off + i) = make_uint2(pack2(l[0], l[1]), pack2(l[2], l[3]));
}

// ---------------- stage load: A 256x16 + Bh/Bl 128x16 fp16 via cp.async ----------------
// Thread pairs (2t,2t+1) cover one row's 32B -> full sectors (proven R11 coalescing).
// Layout: A @ 0, Bh @ A_TILE_B, Bl @ A_TILE_B + B_TILE_B. 4 cp16 per thread.
__device__ __forceinline__ void load_stage(
    uint32_t sb, const __half* __restrict__ Ah,
    const __half* __restrict__ Bh, const __half* __restrict__ Bl,
    int ldA, int ldB, int k0, int tid)
{
#pragma unroll
    for (int it = 0; it < 2; it++) {
        const int idx = tid + it * GEMM_THREADS;       // 0..511 (A has 512 16B-chunks)
        const int row = idx >> 1, part = idx & 1;
        const uint32_t so = (uint32_t)(row * ROW_HALVES + part * 8) * 2;
        cp16(sb + so, Ah + (size_t)row * ldA + k0 + part * 8);
    }
    {
        const int row = tid >> 1, part = tid & 1;      // B tiles: 256 chunks each
        const uint32_t so = (uint32_t)(row * ROW_HALVES + part * 8) * 2;
        const size_t go = (size_t)row * ldB + k0 + part * 8;
        cp16(sb + A_TILE_B + so,            Bh + go);
        cp16(sb + A_TILE_B + B_TILE_B + so, Bl + go);
    }
}

// fragment loads (scalar LDS, conflict-free on 24-half pitch)
#define LOAD_A_FRAGS(dst, st) do { \
    _Pragma("unroll") \
    for (int _mt = 0; _mt < 4; _mt++) { \
        const uint16_t* _p = (st) + (arow + _mt * 16) * ROW_HALVES + kc; \
        (dst)[_mt][0] = *(const uint32_t*)_p; \
        (dst)[_mt][1] = *(const uint32_t*)(_p + 8 * ROW_HALVES); \
        (dst)[_mt][2] = *(const uint32_t*)(_p + 8); \
        (dst)[_mt][3] = *(const uint32_t*)(_p + 8 * ROW_HALVES + 8); \
    } \
} while (0)

#define LOAD_B_FRAGS(st) do { \
    _Pragma("unroll") \
    for (int _nt = 0; _nt < 8; _nt++) { \
        const uint16_t* _p = (st) + A_TILE_HALVES + (brow + _nt * 8) * ROW_HALVES + kc; \
        bh[_nt][0] = *(const uint32_t*)_p; \
        bh[_nt][1] = *(const uint32_t*)(_p + 8); \
        const uint16_t* _q = _p + B_TILE_HALVES; \
        bl[_nt][0] = *(const uint32_t*)_q; \
        bl[_nt][1] = *(const uint32_t*)(_q + 8); \
    } \
} while (0)

// ---------------- warp-MMA mainloop: acc += Ah*(Bh+Bl)^T (2-pass fp16 split) ----------------
// 256x128 CTA tile, 8 warps of 64x64. R11/R14 single-barrier pipeline: CP_WAIT0 +
// __syncthreads publishes stage ic+1 and recycles stage ic; refill streams behind MMAs.
__device__ __forceinline__ void gemm_mainloop(
    const __half* __restrict__ Ah,
    const __half* __restrict__ Bh, const __half* __restrict__ Bl,
    int ldA, int ldB, int nChunks, float acc[4][8][4])
{
    __shared__ __align__(16) uint16_t sm[2 * STAGE_HALVES];   // 49152 B

    const int tid  = threadIdx.x;
    const int lane = tid & 31, warp = tid >> 5;    // 8 warps: 4 rows x 2 cols
    const int wr = warp >> 1, wc = warp & 1;
    const int arow = wr * 64 + (lane >> 2);
    const int brow = wc * 64 + (lane >> 2);
    const int kc   = (lane & 3) * 2;
    const uint32_t sbase = smem_u32(sm);

#pragma unroll
    for (int mt = 0; mt < 4; mt++)
#pragma unroll
        for (int nt = 0; nt < 8; nt++)
#pragma unroll
            for (int e = 0; e < 4; e++) acc[mt][nt][e] = 0.f;

    // prologue: stages 0 and 1 in flight
    load_stage(sbase,           Ah, Bh, Bl, ldA, ldB, 0,      tid); CP_COMMIT();
    load_stage(sbase + STAGE_B, Ah, Bh, Bl, ldA, ldB, KCHUNK, tid); CP_COMMIT();
    CP_WAIT1();            // own stage-0 copies done
    __syncthreads();       // all threads' stage-0 copies visible

    uint32_t a[4][4], bh[8][2], bl[8][2];
    LOAD_A_FRAGS(a, sm);
    LOAD_B_FRAGS(sm);

#pragma unroll 1
    for (int ic = 0; ic < nChunks; ic++) {
#pragma unroll
        for (int mt = 0; mt < 4; mt++)
#pragma unroll
            for (int nt = 0; nt < 8; nt++) MMA(acc[mt][nt], a[mt], bh[nt]);   // Ah*Bh
#pragma unroll
        for (int mt = 0; mt < 4; mt++)
#pragma unroll
            for (int nt = 0; nt < 8; nt++) MMA(acc[mt][nt], a[mt], bl[nt]);   // Ah*Bl

        if (ic + 1 < nChunks) {
            CP_WAIT0();                      // own stage ic+1 copies done
            __syncthreads();                 // publish stage ic+1; stage ic reusable
            const uint16_t* nst = sm + ((ic + 1) & 1) * STAGE_HALVES;
            LOAD_A_FRAGS(a, nst);            // next-chunk fragments (post-barrier: safe)
            LOAD_B_FRAGS(nst);
            if (ic + 2 < nChunks) {          // refill consumed buffer; streams behind MMAs
                load_stage(sbase + (ic & 1) * STAGE_B, Ah, Bh, Bl,
                           ldA, ldB, (ic + 2) * KCHUNK, tid);
                CP_COMMIT();
            }
        }
    }
}

// ---------------- kernel 1: QKV projection ----------------
// z==0 -> Q (hi only); z==1 -> K (hi+lo); z==2 -> V (hi+lo), TRANSPOSED (Vt[b][d][s])
__global__ __launch_bounds__(GEMM_THREADS) void qkv_kernel(
    const float* __restrict__ bq, const float* __restrict__ bk, const float* __restrict__ bv)
{
    const int z = blockIdx.z;
    const int m0 = blockIdx.y * 256, n0 = blockIdx.x * 128;
    const __half* Ah = g_Xh + (size_t)m0 * EMB;
    const __half* Bh = g_Wh + (size_t)z * HDIM * EMB + (size_t)n0 * EMB;
    const __half* Bl = g_Wl + (size_t)z * HDIM * EMB + (size_t)n0 * EMB;

    float acc[4][8][4];
    gemm_mainloop(Ah, Bh, Bl, EMB, EMB, EMB / KCHUNK, acc);

    const float* bias = (z == 0) ? bq : (z == 1) ? bk : bv;
    const int tid = threadIdx.x;
    const int lane = tid & 31, warp = tid >> 5;
    const int wr = warp >> 1, wc = warp & 1;

    if (z == 0) {
        uint16_t* oh = (uint16_t*)g_Qh;
#pragma unroll
        for (int mt = 0; mt < 4; mt++)
#pragma unroll
            for (int nt = 0; nt < 8; nt++) {
                int row0 = wr * 64 + mt * 16 + (lane >> 2);
                int col0 = wc * 64 + nt * 8 + (lane & 3) * 2;
                float b0 = __ldg(&bias[n0 + col0]);
                float b1 = __ldg(&bias[n0 + col0 + 1]);
#pragma unroll
                for (int h = 0; h < 2; h++) {
                    int row = row0 + 8 * h;
                    size_t o = (size_t)(m0 + row) * HDIM + n0 + col0;
                    *(uint32_t*)(oh + o) =
                        pack2(hi16(acc[mt][nt][2*h] + b0), hi16(acc[mt][nt][2*h+1] + b1));
                }
            }
    } else if (z == 1) {
        uint16_t* oh = (uint16_t*)g_Kh;
        uint16_t* ol = (uint16_t*)g_Kl;
#pragma unroll
        for (int mt = 0; mt < 4; mt++)
#pragma unroll
            for (int nt = 0; nt < 8; nt++) {
                int row0 = wr * 64 + mt * 16 + (lane >> 2);
                int col0 = wc * 64 + nt * 8 + (lane & 3) * 2;
                float b0 = __ldg(&bias[n0 + col0]);
                float b1 = __ldg(&bias[n0 + col0 + 1]);
#pragma unroll
                for (int h = 0; h < 2; h++) {
                    int row = row0 + 8 * h;
                    uint16_t h0, l0, h1, l1;
                    split2h(acc[mt][nt][2 * h]     + b0, h0, l0);
                    split2h(acc[mt][nt][2 * h + 1] + b1, h1, l1);
                    size_t o = (size_t)(m0 + row) * HDIM + n0 + col0;
                    *(uint32_t*)(oh + o) = pack2(h0, h1);
                    *(uint32_t*)(ol + o) = pack2(l0, l1);
                }
            }
    } else {
        const int b = m0 >> 11;
        const int s0 = m0 & (SEQ - 1);
        uint16_t* vh = (uint16_t*)g_Vth + ((size_t)b * HDIM + n0) * SEQ + s0;
        uint16_t* vl = (uint16_t*)g_Vtl + ((size_t)b * HDIM + n0) * SEQ + s0;
#pragma unroll
        for (int mt = 0; mt < 4; mt++)
#pragma unroll
            for (int nt = 0; nt < 8; nt++) {
                int row0 = wr * 64 + mt * 16 + (lane >> 2);
                int col0 = wc * 64 + nt * 8 + (lane & 3) * 2;
                float b0 = __ldg(&bias[n0 + col0]);
                float b1 = __ldg(&bias[n0 + col0 + 1]);
#pragma unroll
                for (int h = 0; h < 2; h++) {
                    int row = row0 + 8 * h;         // s coordinate (within 256-row tile)
                    uint16_t h0, l0, h1, l1;
                    split2h(acc[mt][nt][2 * h]     + b0, h0, l0);
                    split2h(acc[mt][nt][2 * h + 1] + b1, h1, l1);
                    vh[(size_t)col0 * SEQ + row]       = h0;
                    vl[(size_t)col0 * SEQ + row]       = l0;
                    vh[(size_t)(col0 + 1) * SEQ + row] = h1;
                    vl[(size_t)(col0 + 1) * SEQ + row] = l1;
                }
            }
    }
}

// ---------------- kernel 2: causal scores ----------------
__global__ __launch_bounds__(GEMM_THREADS) void scores_kernel()
{
    if (blockIdx.x > 2 * blockIdx.y + 1) return;   // fully-masked 256x128 tile
    const int b = blockIdx.z;
    const int m0 = blockIdx.y * 256, n0 = blockIdx.x * 128;
    const __half* Ah = g_Qh + ((size_t)(b * SEQ + m0)) * HDIM;
    const __half* Bh = g_Kh + ((size_t)(b * SEQ + n0)) * HDIM;
    const __half* Bl = g_Kl + ((size_t)(b * SEQ + n0)) * HDIM;

    float acc[4][8][4];
    gemm_mainloop(Ah, Bh, Bl, HDIM, HDIM, HDIM / KCHUNK, acc);

    const int tid = threadIdx.x;
    const int lane = tid & 31, warp = tid >> 5;
    const int wr = warp >> 1, wc = warp & 1;
    const float scale = 0.03125f;   // 1/sqrt(1024)
    float* S = g_S + (size_t)b * SEQ * SEQ;
#pragma unroll
    for (int mt = 0; mt < 4; mt++)
#pragma unroll
        for (int nt = 0; nt < 8; nt++) {
            int row0 = wr * 64 + mt * 16 + (lane >> 2);
            int col0 = wc * 64 + nt * 8 + (lane & 3) * 2;
#pragma unroll
            for (int h = 0; h < 2; h++) {
                int row = row0 + 8 * h;
                float2 v = { acc[mt][nt][2*h] * scale, acc[mt][nt][2*h+1] * scale };
                *(float2*)&S[(size_t)(m0 + row) * SEQ + n0 + col0] = v;
            }
        }
}

// ---------------- kernel 3: softmax -> P hi (contiguous 8 elems/thread) ----------------
__global__ __launch_bounds__(256) void softmax_kernel()
{
    const int rowid = blockIdx.x;
    const int q = rowid & (SEQ - 1);
    const float* s = g_S + (size_t)rowid * SEQ;
    uint16_t* ph = (uint16_t*)g_Ph + (size_t)rowid * SEQ;
    const int valid = q + 1;
    const int tid = threadIdx.x;
    const int i0 = tid * 8;
    __shared__ float red[256];

    float sv[8];
    *(float4*)&sv[0] = *(const float4*)(s + i0);
    *(float4*)&sv[4] = *(const float4*)(s + i0 + 4);

    float mx = -3.0e38f;
#pragma unroll
    for (int k = 0; k < 8; k++) if (i0 + k < valid) mx = fmaxf(mx, sv[k]);
    red[tid] = mx;
    __syncthreads();
    for (int st = 128; st > 0; st >>= 1) {
        if (tid < st) red[tid] = fmaxf(red[tid], red[tid + st]);
        __syncthreads();
    }
    mx = red[0];
    __syncthreads();

    float ev[8];
    float sum = 0.f;
#pragma unroll
    for (int k = 0; k < 8; k++) {
        float e = (i0 + k < valid) ? __expf(sv[k] - mx) : 0.f;
        ev[k] = e; sum += e;
    }
    red[tid] = sum;
    __syncthreads();
    for (int st = 128; st > 0; st >>= 1) {
        if (tid < st) red[tid] += red[tid + st];
        __syncthreads();
    }
    const float inv = 1.0f / red[0];

    uint16_t h[8];
#pragma unroll
    for (int k = 0; k < 8; k++) h[k] = hi16(ev[k] * inv);   // masked ev==0 -> exact 0
    *(uint4*)(ph + i0) = make_uint4(pack2(h[0],h[1]), pack2(h[2],h[3]), pack2(h[4],h[5]), pack2(h[6],h[7]));
}

// ---------------- kernel 4: O = P V (causal-bounded K loop) ----------------
__global__ __launch_bounds__(GEMM_THREADS) void pv_kernel(float* __restrict__ O)
{
    const int b = blockIdx.z;
    const int m0 = blockIdx.y * 256, n0 = blockIdx.x * 128;
    const __half* Ah = g_Ph  + (size_t)b * SEQ * SEQ + (size_t)m0 * SEQ;
    const __half* Bh = g_Vth + ((size_t)b * HDIM + n0) * SEQ;
    const __half* Bl = g_Vtl + ((size_t)b * HDIM + n0) * SEQ;
    const int nChunks = m0 / KCHUNK + 16;   // K in [0, m0+256)

    float acc[4][8][4];
    gemm_mainloop(Ah, Bh, Bl, SEQ, SEQ, nChunks, acc);

    const int tid = threadIdx.x;
    const int lane = tid & 31, warp = tid >> 5;
    const int wr = warp >> 1, wc = warp & 1;
    float* C = O + (size_t)b * SEQ * HDIM;
#pragma unroll
    for (int mt = 0; mt < 4; mt++)
#pragma unroll
        for (int nt = 0; nt < 8; nt++) {
            int row0 = wr * 64 + mt * 16 + (lane >> 2);
            int col0 = wc * 64 + nt * 8 + (lane & 3) * 2;
#pragma unroll
            for (int h = 0; h < 2; h++) {
                int row = row0 + 8 * h;
                float2 v = { acc[mt][nt][2*h], acc[mt][nt][2*h+1] };
                *(float2*)&C[(size_t)(m0 + row) * HDIM + n0 + col0] = v;
            }
        }
}

// ---------------- launch: kernel launches ONLY ----------------
extern "C" void kernel_launch(void* const* d_in, const int* in_sizes, int n_in,
                              void* d_out, int out_size)
{
    (void)in_sizes; (void)n_in; (void)out_size;
    const float* X  = (const float*)d_in[0];
    const float* Wq = (const float*)d_in[1];
    const float* bq = (const float*)d_in[2];
    const float* Wk = (const float*)d_in[3];
    const float* bk = (const float*)d_in[4];
    const float* Wv = (const float*)d_in[5];
    const float* bv = (const float*)d_in[6];
    float* out = (float*)d_out;

    split_x_kernel<<<(MROWS * EMB) / 1024, 256>>>(X);
    split_w_kernel<<<dim3((HDIM * EMB) / 1024, 3), 256>>>(Wq, Wk, Wv);

    qkv_kernel<<<dim3(HDIM / 128, MROWS / 256, 3), GEMM_THREADS>>>(bq, bk, bv);
    scores_kernel<<<dim3(SEQ / 128, SEQ / 256, BATCH), GEMM_THREADS>>>();
    softmax_kernel<<<MROWS, 256>>>();
    pv_kernel<<<dim3(HDIM / 128, SEQ / 256, BATCH), GEMM_THREADS>>>(out);
}

// round 17
// speedup vs baseline: 1.3179x; 1.3179x over previous
#include <cuda_runtime.h>
#include <cuda_fp16.h>
#include <cstdint>

#define BATCH 4
#define SEQ   2048
#define EMB   1024
#define HDIM  1024
#define MROWS (BATCH*SEQ)

#define KCHUNK       16
#define ROW_HALVES   24                       // 16 data halves + 8 pad (48B pitch, conflict-free)
#define TILE_HALVES  (128*ROW_HALVES)         // 3072 halves = 6144 B
#define TILE_B       (TILE_HALVES*2)

#define GEMM_THREADS 128                      // 4 warps of 64x64 (proven R14 config)

// ---------------- device scratch ----------------
__device__ __half g_Xh [(size_t)MROWS*EMB];                // X hi only
__device__ __half g_Wh [(size_t)3*HDIM*EMB];               // W hi only (1-pass QKV)
__device__ __half g_Qh [(size_t)MROWS*HDIM];               // Q hi only (A side)
__device__ __half g_Kh [(size_t)MROWS*HDIM];               // K split storage
__device__ __half g_Kl [(size_t)MROWS*HDIM];
__device__ __half g_Vth[(size_t)BATCH*HDIM*SEQ];           // V split, transposed [b][d][s]
__device__ __half g_Vtl[(size_t)BATCH*HDIM*SEQ];
__device__ float  g_S  [(size_t)BATCH*SEQ*SEQ];
__device__ __half g_Ph [(size_t)BATCH*SEQ*SEQ];            // P hi only (A side)

// ---------------- helpers ----------------
__device__ __forceinline__ uint32_t smem_u32(const void* p) {
    uint32_t a;
    asm("{ .reg .u64 t; cvta.to.shared.u64 t, %1; cvt.u32.u64 %0, t; }" : "=r"(a) : "l"(p));
    return a;
}
__device__ __forceinline__ void cp16(uint32_t saddr, const void* g) {
    asm volatile("cp.async.cg.shared.global [%0], [%1], 16;" :: "r"(saddr), "l"(g));
}
#define CP_COMMIT() asm volatile("cp.async.commit_group;" ::: "memory")
#define CP_WAIT1()  asm volatile("cp.async.wait_group 1;" ::: "memory")
#define CP_WAIT0()  asm volatile("cp.async.wait_group 0;" ::: "memory")

#define MMA(c, a, b) \
    asm volatile("mma.sync.aligned.m16n8k16.row.col.f32.f16.f16.f32 " \
        "{%0,%1,%2,%3}, {%4,%5,%6,%7}, {%8,%9}, {%0,%1,%2,%3};" \
        : "+f"((c)[0]), "+f"((c)[1]), "+f"((c)[2]), "+f"((c)[3]) \
        : "r"((a)[0]), "r"((a)[1]), "r"((a)[2]), "r"((a)[3]), "r"((b)[0]), "r"((b)[1]))

__device__ __forceinline__ uint16_t hi16(float x) {
    return __half_as_ushort(__float2half(x));
}
__device__ __forceinline__ void split2h(float x, uint16_t& h, uint16_t& l) {
    __half hb = __float2half(x);
    __half lb = __float2half(x - __half2float(hb));
    h = __half_as_ushort(hb);
    l = __half_as_ushort(lb);
}
__device__ __forceinline__ uint32_t pack2(uint16_t a, uint16_t b) {
    return (uint32_t)a | ((uint32_t)b << 16);
}

// ---------------- split kernels ----------------
__global__ __launch_bounds__(256) void split_x_kernel(const float* __restrict__ src) {
    size_t i = ((size_t)blockIdx.x * 256 + threadIdx.x) * 4;
    float4 v = *(const float4*)(src + i);
    *(uint2*)((uint16_t*)g_Xh + i) =
        make_uint2(pack2(hi16(v.x), hi16(v.y)), pack2(hi16(v.z), hi16(v.w)));
}
__global__ __launch_bounds__(256) void split_w_kernel(
    const float* __restrict__ Wq, const float* __restrict__ Wk, const float* __restrict__ Wv)
{
    const int z = blockIdx.y;
    const float* src = (z == 0) ? Wq : (z == 1) ? Wk : Wv;
    size_t i = ((size_t)blockIdx.x * 256 + threadIdx.x) * 4;
    size_t off = (size_t)z * HDIM * EMB;
    float4 v = *(const float4*)(src + i);
    *(uint2*)((uint16_t*)g_Wh + off + i) =
        make_uint2(pack2(hi16(v.x), hi16(v.y)), pack2(hi16(v.z), hi16(v.w)));
}

// ---------------- stage load (templated): A + Bh [+ Bl], 128x16 fp16 tiles ----------------
// Thread pairs (2t,2t+1) cover one row's 32B -> full sectors (proven coalescing).
template<bool SPLITB>
__device__ __forceinline__ void load_stage(
    uint32_t sb, const __half* __restrict__ Ah,
    const __half* __restrict__ Bh, const __half* __restrict__ Bl,
    int ldA, int ldB, int k0, int tid)
{
#pragma unroll
    for (int it = 0; it < 2; it++) {
        const int idx = tid + it * GEMM_THREADS;       // 0..255 16B-chunks per tile
        const int row = idx >> 1, part = idx & 1;
        const uint32_t so = (uint32_t)(row * ROW_HALVES + part * 8) * 2;
        const size_t goA = (size_t)row * ldA + k0 + part * 8;
        const size_t goB = (size_t)row * ldB + k0 + part * 8;
        cp16(sb + so,              Ah + goA);
        cp16(sb + TILE_B + so,     Bh + goB);
        if (SPLITB) cp16(sb + 2 * TILE_B + so, Bl + goB);
    }
}

// fragment loads (scalar LDS, conflict-free on 24-half pitch)
#define LOAD_A_FRAGS(dst, st) do { \
    _Pragma("unroll") \
    for (int _mt = 0; _mt < 4; _mt++) { \
        const uint16_t* _p = (st) + (arow + _mt * 16) * ROW_HALVES + kc; \
        (dst)[_mt][0] = *(const uint32_t*)_p; \
        (dst)[_mt][1] = *(const uint32_t*)(_p + 8 * ROW_HALVES); \
        (dst)[_mt][2] = *(const uint32_t*)(_p + 8); \
        (dst)[_mt][3] = *(const uint32_t*)(_p + 8 * ROW_HALVES + 8); \
    } \
} while (0)

#define LOAD_BH_FRAGS(st) do { \
    _Pragma("unroll") \
    for (int _nt = 0; _nt < 8; _nt++) { \
        const uint16_t* _p = (st) + TILE_HALVES + (brow + _nt * 8) * ROW_HALVES + kc; \
        bh[_nt][0] = *(const uint32_t*)_p; \
        bh[_nt][1] = *(const uint32_t*)(_p + 8); \
    } \
} while (0)

#define LOAD_BL_FRAGS(st) do { \
    _Pragma("unroll") \
    for (int _nt = 0; _nt < 8; _nt++) { \
        const uint16_t* _q = (st) + 2 * TILE_HALVES + (brow + _nt * 8) * ROW_HALVES + kc; \
        bl[_nt][0] = *(const uint32_t*)_q; \
        bl[_nt][1] = *(const uint32_t*)(_q + 8); \
    } \
} while (0)

// ---------------- warp-MMA mainloop (templated on B-split) ----------------
// 128x128 CTA tile, 4 warps of 64x64. Proven R14 single-barrier pipeline:
// CP_WAIT0 + __syncthreads publishes next stage and recycles the old one.
template<bool SPLITB>
__device__ __forceinline__ void gemm_mainloop(
    const __half* __restrict__ Ah,
    const __half* __restrict__ Bh, const __half* __restrict__ Bl,
    int ldA, int ldB, int nChunks, float acc[4][8][4])
{
    constexpr int NT = SPLITB ? 3 : 2;
    constexpr int STG_HALVES = NT * TILE_HALVES;
    constexpr int STG_B = STG_HALVES * 2;
    __shared__ __align__(16) uint16_t sm[2 * STG_HALVES];   // 36864 B (split) / 24576 B

    const int tid  = threadIdx.x;
    const int lane = tid & 31, warp = tid >> 5;    // 4 warps: 2x2
    const int wr = warp >> 1, wc = warp & 1;
    const int arow = wr * 64 + (lane >> 2);
    const int brow = wc * 64 + (lane >> 2);
    const int kc   = (lane & 3) * 2;
    const uint32_t sbase = smem_u32(sm);

#pragma unroll
    for (int mt = 0; mt < 4; mt++)
#pragma unroll
        for (int nt = 0; nt < 8; nt++)
#pragma unroll
            for (int e = 0; e < 4; e++) acc[mt][nt][e] = 0.f;

    // prologue: stages 0 and 1 in flight
    load_stage<SPLITB>(sbase,         Ah, Bh, Bl, ldA, ldB, 0,      tid); CP_COMMIT();
    load_stage<SPLITB>(sbase + STG_B, Ah, Bh, Bl, ldA, ldB, KCHUNK, tid); CP_COMMIT();
    CP_WAIT1();            // own stage-0 copies done
    __syncthreads();       // all threads' stage-0 copies visible

    uint32_t a[4][4], bh[8][2], bl[8][2];
    LOAD_A_FRAGS(a, sm);
    LOAD_BH_FRAGS(sm);
    if (SPLITB) LOAD_BL_FRAGS(sm);

#pragma unroll 1
    for (int ic = 0; ic < nChunks; ic++) {
#pragma unroll
        for (int mt = 0; mt < 4; mt++)
#pragma unroll
            for (int nt = 0; nt < 8; nt++) MMA(acc[mt][nt], a[mt], bh[nt]);   // A*Bh
        if (SPLITB) {
#pragma unroll
            for (int mt = 0; mt < 4; mt++)
#pragma unroll
                for (int nt = 0; nt < 8; nt++) MMA(acc[mt][nt], a[mt], bl[nt]);   // A*Bl
        }

        if (ic + 1 < nChunks) {
            CP_WAIT0();                      // own stage ic+1 copies done
            __syncthreads();                 // publish stage ic+1; stage ic reusable
            const uint16_t* nst = sm + ((ic + 1) & 1) * STG_HALVES;
            LOAD_A_FRAGS(a, nst);            // next-chunk fragments (post-barrier: safe)
            LOAD_BH_FRAGS(nst);
            if (SPLITB) LOAD_BL_FRAGS(nst);
            if (ic + 2 < nChunks) {          // refill consumed buffer; streams behind MMAs
                load_stage<SPLITB>(sbase + (ic & 1) * STG_B, Ah, Bh, Bl,
                                   ldA, ldB, (ic + 2) * KCHUNK, tid);
                CP_COMMIT();
            }
        }
    }
}

// ---------------- kernel 1: QKV projection (1-pass: X_h * W_h) ----------------
// z==0 -> Q (hi only); z==1 -> K (split storage); z==2 -> V (split, TRANSPOSED Vt[b][d][s])
__global__ __launch_bounds__(GEMM_THREADS) void qkv_kernel(
    const float* __restrict__ bq, const float* __restrict__ bk, const float* __restrict__ bv)
{
    const int z = blockIdx.z;
    const int m0 = blockIdx.y * 128, n0 = blockIdx.x * 128;
    const __half* Ah = g_Xh + (size_t)m0 * EMB;
    const __half* Bh = g_Wh + (size_t)z * HDIM * EMB + (size_t)n0 * EMB;

    float acc[4][8][4];
    gemm_mainloop<false>(Ah, Bh, Bh, EMB, EMB, EMB / KCHUNK, acc);

    const float* bias = (z == 0) ? bq : (z == 1) ? bk : bv;
    const int tid = threadIdx.x;
    const int lane = tid & 31, warp = tid >> 5;
    const int wr = warp >> 1, wc = warp & 1;

    if (z == 0) {
        uint16_t* oh = (uint16_t*)g_Qh;
#pragma unroll
        for (int mt = 0; mt < 4; mt++)
#pragma unroll
            for (int nt = 0; nt < 8; nt++) {
                int row0 = wr * 64 + mt * 16 + (lane >> 2);
                int col0 = wc * 64 + nt * 8 + (lane & 3) * 2;
                float b0 = __ldg(&bias[n0 + col0]);
                float b1 = __ldg(&bias[n0 + col0 + 1]);
#pragma unroll
                for (int h = 0; h < 2; h++) {
                    int row = row0 + 8 * h;
                    size_t o = (size_t)(m0 + row) * HDIM + n0 + col0;
                    *(uint32_t*)(oh + o) =
                        pack2(hi16(acc[mt][nt][2*h] + b0), hi16(acc[mt][nt][2*h+1] + b1));
                }
            }
    } else if (z == 1) {
        uint16_t* oh = (uint16_t*)g_Kh;
        uint16_t* ol = (uint16_t*)g_Kl;
#pragma unroll
        for (int mt = 0; mt < 4; mt++)
#pragma unroll
            for (int nt = 0; nt < 8; nt++) {
                int row0 = wr * 64 + mt * 16 + (lane >> 2);
                int col0 = wc * 64 + nt * 8 + (lane & 3) * 2;
                float b0 = __ldg(&bias[n0 + col0]);
                float b1 = __ldg(&bias[n0 + col0 + 1]);
#pragma unroll
                for (int h = 0; h < 2; h++) {
                    int row = row0 + 8 * h;
                    uint16_t h0, l0, h1, l1;
                    split2h(acc[mt][nt][2 * h]     + b0, h0, l0);
                    split2h(acc[mt][nt][2 * h + 1] + b1, h1, l1);
                    size_t o = (size_t)(m0 + row) * HDIM + n0 + col0;
                    *(uint32_t*)(oh + o) = pack2(h0, h1);
                    *(uint32_t*)(ol + o) = pack2(l0, l1);
                }
            }
    } else {
        const int b = m0 >> 11;
        const int s0 = m0 & (SEQ - 1);
        uint16_t* vh = (uint16_t*)g_Vth + ((size_t)b * HDIM + n0) * SEQ + s0;
        uint16_t* vl = (uint16_t*)g_Vtl + ((size_t)b * HDIM + n0) * SEQ + s0;
#pragma unroll
        for (int mt = 0; mt < 4; mt++)
#pragma unroll
            for (int nt = 0; nt < 8; nt++) {
                int row0 = wr * 64 + mt * 16 + (lane >> 2);
                int col0 = wc * 64 + nt * 8 + (lane & 3) * 2;
                float b0 = __ldg(&bias[n0 + col0]);
                float b1 = __ldg(&bias[n0 + col0 + 1]);
#pragma unroll
                for (int h = 0; h < 2; h++) {
                    int row = row0 + 8 * h;         // s coordinate
                    uint16_t h0, l0, h1, l1;
                    split2h(acc[mt][nt][2 * h]     + b0, h0, l0);
                    split2h(acc[mt][nt][2 * h + 1] + b1, h1, l1);
                    vh[(size_t)col0 * SEQ + row]       = h0;
                    vl[(size_t)col0 * SEQ + row]       = l0;
                    vh[(size_t)(col0 + 1) * SEQ + row] = h1;
                    vl[(size_t)(col0 + 1) * SEQ + row] = l1;
                }
            }
    }
}

// ---------------- kernel 2: causal scores (2-pass: Q_h * (K_h + K_l)) ----------------
__global__ __launch_bounds__(GEMM_THREADS) void scores_kernel()
{
    if (blockIdx.x > blockIdx.y) return;   // fully-masked tile
    const int b = blockIdx.z;
    const int m0 = blockIdx.y * 128, n0 = blockIdx.x * 128;
    const __half* Ah = g_Qh + ((size_t)(b * SEQ + m0)) * HDIM;
    const __half* Bh = g_Kh + ((size_t)(b * SEQ + n0)) * HDIM;
    const __half* Bl = g_Kl + ((size_t)(b * SEQ + n0)) * HDIM;

    float acc[4][8][4];
    gemm_mainloop<true>(Ah, Bh, Bl, HDIM, HDIM, HDIM / KCHUNK, acc);

    const int tid = threadIdx.x;
    const int lane = tid & 31, warp = tid >> 5;
    const int wr = warp >> 1, wc = warp & 1;
    const float scale = 0.03125f;   // 1/sqrt(1024)
    float* S = g_S + (size_t)b * SEQ * SEQ;
#pragma unroll
    for (int mt = 0; mt < 4; mt++)
#pragma unroll
        for (int nt = 0; nt < 8; nt++) {
            int row0 = wr * 64 + mt * 16 + (lane >> 2);
            int col0 = wc * 64 + nt * 8 + (lane & 3) * 2;
#pragma unroll
            for (int h = 0; h < 2; h++) {
                int row = row0 + 8 * h;
                float2 v = { acc[mt][nt][2*h] * scale, acc[mt][nt][2*h+1] * scale };
                *(float2*)&S[(size_t)(m0 + row) * SEQ + n0 + col0] = v;
            }
        }
}

// ---------------- kernel 3: softmax -> P hi (contiguous 8 elems/thread) ----------------
__global__ __launch_bounds__(256) void softmax_kernel()
{
    const int rowid = blockIdx.x;
    const int q = rowid & (SEQ - 1);
    const float* s = g_S + (size_t)rowid * SEQ;
    uint16_t* ph = (uint16_t*)g_Ph + (size_t)rowid * SEQ;
    const int valid = q + 1;
    const int tid = threadIdx.x;
    const int i0 = tid * 8;
    __shared__ float red[256];

    float sv[8];
    *(float4*)&sv[0] = *(const float4*)(s + i0);
    *(float4*)&sv[4] = *(const float4*)(s + i0 + 4);

    float mx = -3.0e38f;
#pragma unroll
    for (int k = 0; k < 8; k++) if (i0 + k < valid) mx = fmaxf(mx, sv[k]);
    red[tid] = mx;
    __syncthreads();
    for (int st = 128; st > 0; st >>= 1) {
        if (tid < st) red[tid] = fmaxf(red[tid], red[tid + st]);
        __syncthreads();
    }
    mx = red[0];
    __syncthreads();

    float ev[8];
    float sum = 0.f;
#pragma unroll
    for (int k = 0; k < 8; k++) {
        float e = (i0 + k < valid) ? __expf(sv[k] - mx) : 0.f;
        ev[k] = e; sum += e;
    }
    red[tid] = sum;
    __syncthreads();
    for (int st = 128; st > 0; st >>= 1) {
        if (tid < st) red[tid] += red[tid + st];
        __syncthreads();
    }
    const float inv = 1.0f / red[0];

    uint16_t h[8];
#pragma unroll
    for (int k = 0; k < 8; k++) h[k] = hi16(ev[k] * inv);   // masked ev==0 -> exact 0
    *(uint4*)(ph + i0) = make_uint4(pack2(h[0],h[1]), pack2(h[2],h[3]), pack2(h[4],h[5]), pack2(h[6],h[7]));
}

// ---------------- kernel 4: O = P V (2-pass: P_h * (V_h + V_l), causal K bound) ----------------
__global__ __launch_bounds__(GEMM_THREADS) void pv_kernel(float* __restrict__ O)
{
    const int b = blockIdx.z;
    const int m0 = blockIdx.y * 128, n0 = blockIdx.x * 128;
    const __half* Ah = g_Ph  + (size_t)b * SEQ * SEQ + (size_t)m0 * SEQ;
    const __half* Bh = g_Vth + ((size_t)b * HDIM + n0) * SEQ;
    const __half* Bl = g_Vtl + ((size_t)b * HDIM + n0) * SEQ;
    const int nChunks = m0 / KCHUNK + 8;   // K in [0, m0+128)

    float acc[4][8][4];
    gemm_mainloop<true>(Ah, Bh, Bl, SEQ, SEQ, nChunks, acc);

    const int tid = threadIdx.x;
    const int lane = tid & 31, warp = tid >> 5;
    const int wr = warp >> 1, wc = warp & 1;
    float* C = O + (size_t)b * SEQ * HDIM;
#pragma unroll
    for (int mt = 0; mt < 4; mt++)
#pragma unroll
        for (int nt = 0; nt < 8; nt++) {
            int row0 = wr * 64 + mt * 16 + (lane >> 2);
            int col0 = wc * 64 + nt * 8 + (lane & 3) * 2;
#pragma unroll
            for (int h = 0; h < 2; h++) {
                int row = row0 + 8 * h;
                float2 v = { acc[mt][nt][2*h], acc[mt][nt][2*h+1] };
                *(float2*)&C[(size_t)(m0 + row) * HDIM + n0 + col0] = v;
            }
        }
}

// ---------------- launch: kernel launches ONLY ----------------
extern "C" void kernel_launch(void* const* d_in, const int* in_sizes, int n_in,
                              void* d_out, int out_size)
{
    (void)in_sizes; (void)n_in; (void)out_size;
    const float* X  = (const float*)d_in[0];
    const float* Wq = (const float*)d_in[1];
    const float* bq = (const float*)d_in[2];
    const float* Wk = (const float*)d_in[3];
    const float* bk = (const float*)d_in[4];
    const float* Wv = (const float*)d_in[5];
    const float* bv = (const float*)d_in[6];
    float* out = (float*)d_out;

    split_x_kernel<<<(MROWS * EMB) / 1024, 256>>>(X);
    split_w_kernel<<<dim3((HDIM * EMB) / 1024, 3), 256>>>(Wq, Wk, Wv);

    qkv_kernel<<<dim3(HDIM / 128, MROWS / 128, 3), GEMM_THREADS>>>(bq, bk, bv);
    scores_kernel<<<dim3(SEQ / 128, SEQ / 128, BATCH), GEMM_THREADS>>>();
    softmax_kernel<<<MROWS, 256>>>();
    pv_kernel<<<dim3(HDIM / 128, SEQ / 128, BATCH), GEMM_THREADS>>>(out);
}